// round 9
// baseline (speedup 1.0000x reference)
#include <cuda_runtime.h>

// Problem constants (fixed by the dataset)
#define B_   4
#define N_   4096
#define H_   16
#define D_   64
#define ROWS (B_ * N_ * H_)          // 262144 rows, one warp each
#define SM_SCALE 0.125f              // 1/sqrt(64)
#define EPS_ 1e-9f

// Warp-per-row, float2 per lane, default cache policy — the reproducibly
// fastest harness structure (78.34/78.56 vs 79.7-80.1 for all f4 variants).
// R9: 512-thread blocks for a wider contiguous per-block DRAM footprint.
__global__ __launch_bounds__(512)
void hier_attn_kernel(const float* __restrict__ Qp,
                      const float* __restrict__ Kp,
                      const float* __restrict__ Vp,
                      const float* __restrict__ Kc,
                      const float* __restrict__ Vc,
                      float* __restrict__ out,
                      float* __restrict__ w_out) {
    const int gwarp = (blockIdx.x * blockDim.x + threadIdx.x) >> 5;
    const int lane  = threadIdx.x & 31;

    // gwarp = (b*N + n)*H + h
    const int h  = gwarp & (H_ - 1);
    const int bn = gwarp >> 4;       // b*N + n   (H_ = 16)
    const int n  = bn & (N_ - 1);
    const int b  = bn >> 12;         // N_ = 4096

    // parent-layout offset: [b, n, h, d] with d contiguous -> gwarp * D
    const int p_off  = gwarp * D_;
    // child-layout offset: [b, 2n+c, h, d]
    const int c0_off = (((b * (2 * N_) + 2 * n) * H_) + h) * D_;
    const int c1_off = c0_off + H_ * D_;

    // All 7 vector loads front-batched (float2 per lane => 256B coalesced each)
    const float2 q   = reinterpret_cast<const float2*>(Qp + p_off)[lane];
    const float2 kp  = reinterpret_cast<const float2*>(Kp + p_off)[lane];
    const float2 kc0 = reinterpret_cast<const float2*>(Kc + c0_off)[lane];
    const float2 kc1 = reinterpret_cast<const float2*>(Kc + c1_off)[lane];
    const float2 vp  = reinterpret_cast<const float2*>(Vp + p_off)[lane];
    const float2 vc0 = reinterpret_cast<const float2*>(Vc + c0_off)[lane];
    const float2 vc1 = reinterpret_cast<const float2*>(Vc + c1_off)[lane];

    // Three partial dot products
    float s0 = q.x * kp.x  + q.y * kp.y;
    float s1 = q.x * kc0.x + q.y * kc0.y;
    float s2 = q.x * kc1.x + q.y * kc1.y;

    // Butterfly reduction across the warp (all lanes end with full sums)
    #pragma unroll
    for (int m = 16; m > 0; m >>= 1) {
        s0 += __shfl_xor_sync(0xFFFFFFFFu, s0, m);
        s1 += __shfl_xor_sync(0xFFFFFFFFu, s1, m);
        s2 += __shfl_xor_sync(0xFFFFFFFFu, s2, m);
    }

    s0 *= SM_SCALE;
    s1 *= SM_SCALE;
    s2 *= SM_SCALE;

    // 3-way softmax with +eps in denominator (matches reference)
    const float mx = fmaxf(s0, fmaxf(s1, s2));
    const float e0 = expf(s0 - mx);
    const float e1 = expf(s1 - mx);
    const float e2 = expf(s2 - mx);
    const float inv = 1.0f / (e0 + e1 + e2 + EPS_);
    const float w0 = e0 * inv;
    const float w1 = e1 * inv;
    const float w2 = e2 * inv;

    // Weighted V combine, coalesced float2 store
    float2 o;
    o.x = w0 * vp.x + w1 * vc0.x + w2 * vc1.x;
    o.y = w0 * vp.y + w1 * vc0.y + w2 * vc1.y;
    reinterpret_cast<float2*>(out + p_off)[lane] = o;

    // w output: [b,n,h,3] raveled after out
    if (lane < 3) {
        const float wv = (lane == 0) ? w0 : (lane == 1) ? w1 : w2;
        w_out[gwarp * 3 + lane] = wv;
    }
}

extern "C" void kernel_launch(void* const* d_in, const int* in_sizes, int n_in,
                              void* d_out, int out_size) {
    const float* Qp = (const float*)d_in[0];
    const float* Kp = (const float*)d_in[1];
    const float* Vp = (const float*)d_in[2];
    const float* Kc = (const float*)d_in[3];
    const float* Vc = (const float*)d_in[4];

    float* out   = (float*)d_out;
    float* w_out = out + (size_t)ROWS * D_;   // w follows out in the output buffer

    const int threads = 512;                   // 16 warps/block
    const int blocks  = (ROWS * 32) / threads; // 16384
    hier_attn_kernel<<<blocks, threads>>>(Qp, Kp, Vp, Kc, Vc, out, w_out);
}

// round 10
// speedup vs baseline: 1.0266x; 1.0266x over previous
#include <cuda_runtime.h>

// Problem constants (fixed by the dataset)
#define B_   4
#define N_   4096
#define H_   16
#define D_   64
#define ROWS (B_ * N_ * H_)          // 262144 rows, one warp each
#define SM_SCALE 0.125f              // 1/sqrt(64)
#define EPS_ 1e-9f

// Warp-per-row, float2 per lane, default cache policy.
// Harness evidence: 256-thd blocks -> 78.34/78.56; 512-thd -> 80.4;
// f4 variants -> 79.7-80.1. Gradient points to smaller blocks: probe 128.
__global__ __launch_bounds__(128)
void hier_attn_kernel(const float* __restrict__ Qp,
                      const float* __restrict__ Kp,
                      const float* __restrict__ Vp,
                      const float* __restrict__ Kc,
                      const float* __restrict__ Vc,
                      float* __restrict__ out,
                      float* __restrict__ w_out) {
    const int gwarp = (blockIdx.x * blockDim.x + threadIdx.x) >> 5;
    const int lane  = threadIdx.x & 31;

    // gwarp = (b*N + n)*H + h
    const int h  = gwarp & (H_ - 1);
    const int bn = gwarp >> 4;       // b*N + n   (H_ = 16)
    const int n  = bn & (N_ - 1);
    const int b  = bn >> 12;         // N_ = 4096

    // parent-layout offset: [b, n, h, d] with d contiguous -> gwarp * D
    const int p_off  = gwarp * D_;
    // child-layout offset: [b, 2n+c, h, d]
    const int c0_off = (((b * (2 * N_) + 2 * n) * H_) + h) * D_;
    const int c1_off = c0_off + H_ * D_;

    // All 7 vector loads front-batched (float2 per lane => 256B coalesced each)
    const float2 q   = reinterpret_cast<const float2*>(Qp + p_off)[lane];
    const float2 kp  = reinterpret_cast<const float2*>(Kp + p_off)[lane];
    const float2 kc0 = reinterpret_cast<const float2*>(Kc + c0_off)[lane];
    const float2 kc1 = reinterpret_cast<const float2*>(Kc + c1_off)[lane];
    const float2 vp  = reinterpret_cast<const float2*>(Vp + p_off)[lane];
    const float2 vc0 = reinterpret_cast<const float2*>(Vc + c0_off)[lane];
    const float2 vc1 = reinterpret_cast<const float2*>(Vc + c1_off)[lane];

    // Three partial dot products
    float s0 = q.x * kp.x  + q.y * kp.y;
    float s1 = q.x * kc0.x + q.y * kc0.y;
    float s2 = q.x * kc1.x + q.y * kc1.y;

    // Butterfly reduction across the warp (all lanes end with full sums)
    #pragma unroll
    for (int m = 16; m > 0; m >>= 1) {
        s0 += __shfl_xor_sync(0xFFFFFFFFu, s0, m);
        s1 += __shfl_xor_sync(0xFFFFFFFFu, s1, m);
        s2 += __shfl_xor_sync(0xFFFFFFFFu, s2, m);
    }

    s0 *= SM_SCALE;
    s1 *= SM_SCALE;
    s2 *= SM_SCALE;

    // 3-way softmax with +eps in denominator (matches reference)
    const float mx = fmaxf(s0, fmaxf(s1, s2));
    const float e0 = expf(s0 - mx);
    const float e1 = expf(s1 - mx);
    const float e2 = expf(s2 - mx);
    const float inv = 1.0f / (e0 + e1 + e2 + EPS_);
    const float w0 = e0 * inv;
    const float w1 = e1 * inv;
    const float w2 = e2 * inv;

    // Weighted V combine, coalesced float2 store
    float2 o;
    o.x = w0 * vp.x + w1 * vc0.x + w2 * vc1.x;
    o.y = w0 * vp.y + w1 * vc0.y + w2 * vc1.y;
    reinterpret_cast<float2*>(out + p_off)[lane] = o;

    // w output: [b,n,h,3] raveled after out
    if (lane < 3) {
        const float wv = (lane == 0) ? w0 : (lane == 1) ? w1 : w2;
        w_out[gwarp * 3 + lane] = wv;
    }
}

extern "C" void kernel_launch(void* const* d_in, const int* in_sizes, int n_in,
                              void* d_out, int out_size) {
    const float* Qp = (const float*)d_in[0];
    const float* Kp = (const float*)d_in[1];
    const float* Vp = (const float*)d_in[2];
    const float* Kc = (const float*)d_in[3];
    const float* Vc = (const float*)d_in[4];

    float* out   = (float*)d_out;
    float* w_out = out + (size_t)ROWS * D_;   // w follows out in the output buffer

    const int threads = 128;                   // 4 warps/block
    const int blocks  = (ROWS * 32) / threads; // 65536
    hier_attn_kernel<<<blocks, threads>>>(Qp, Kp, Vp, Kc, Vc, out, w_out);
}